// round 3
// baseline (speedup 1.0000x reference)
#include <cuda_runtime.h>
#include <cstdint>

// out[b,c,h,w] = x[b,c,2h,2w] * 0.5f
// x:  [16, 64, 512, 512] fp32   (contiguous, W innermost)
// out:[16, 64, 256, 256] fp32
//
// Each thread: one float4 load from an even input row (covers input cols
// 4p..4p+3), emits float2 {v.x, v.z} * 0.5 to output cols 2p, 2p+1.
//
// Index math (all powers of two -> shifts):
//   pair  p   in [0,128)   : which float2 of the output row
//   orow  r   in [0,256)   : output row
//   bc        in [0,1024)  : fused batch*channel
//   in  float4 idx = bc*65536 + r*256 + p      (512*512/4 = 65536, 512/... per row: 512 floats = 128 float4; 2r*128 = r*256)
//   out float2 idx = global thread idx

__global__ __launch_bounds__(256) void haar_sum_kernel(
    const float4* __restrict__ x, float2* __restrict__ out, long long n_pairs)
{
    long long i = (long long)blockIdx.x * blockDim.x + threadIdx.x;
    if (i >= n_pairs) return;

    // decompose i -> (bc, orow, pair)
    long long pair = i & 127;           // i % 128
    long long orow = (i >> 7) & 255;    // (i/128) % 256
    long long bc   = i >> 15;           // i / (128*256)

    // input float4 index: bc * (512*512/4) + (2*orow) * (512/4) + pair
    long long in_idx = (bc << 16) + (orow << 8) + pair;

    float4 v = __ldcs(&x[in_idx]);      // streaming: no reuse
    float2 o;
    o.x = v.x * 0.5f;
    o.y = v.z * 0.5f;
    __stcs(&out[i], o);
}

extern "C" void kernel_launch(void* const* d_in, const int* in_sizes, int n_in,
                              void* d_out, int out_size)
{
    const float4* x  = (const float4*)d_in[0];
    float2* out      = (float2*)d_out;

    // out_size = 16*64*256*256 = 67,108,864 floats -> 33,554,432 float2 pairs
    long long n_pairs = (long long)out_size / 2;

    const int threads = 256;
    long long blocks = (n_pairs + threads - 1) / threads;   // 131072

    haar_sum_kernel<<<(unsigned)blocks, threads>>>(x, out, n_pairs);
}